// round 3
// baseline (speedup 1.0000x reference)
#include <cuda_runtime.h>

// Problem shape (fixed by the dataset)
#define BB 4
#define SS 256
#define EE 256
#define MM (BB * SS)        // 1024 rows of x

// Scratch + sync state
__device__ float g_pi [MM * EE];
__device__ float g_pjb[MM * EE];
__device__ volatile int g_b_done[BB];   // per-b completed gemm tiles
__device__ unsigned g_exit_cnt;

// ---- gemm (producer) config ----
#define GW    128                 // producer blocks
#define GSTG  2                   // sequential tiles per producer
#define BM    16
#define BN    64
#define BK    32
#define NT    (EE / BK)           // 8 K-chunks
#define BTGT  64                  // tiles per b: (256/BM)=16 m-tiles x 4 f-tiles

#define XS 20                     // s_x row stride (floats)
#define WS 68                     // s_w row stride (floats), float4-aligned

// ---- add (consumer) config ----
#define TI 8
#define TJ 32
#define E4 (EE / 4)
#define NA 1024                   // (256/TI)*(256/TJ)*BB
#define GTOT (GW + NA)

union Smem {
    struct {
        float x [BK][XS];         // 2.5 KB
        float w1[BK][WS];         // 8.5 KB
        float w2[BK][WS];         // 8.5 KB
    } g;
    float4 pj[TJ * E4];           // 32 KB
};

__global__ __launch_bounds__(256)
void fused_kernel(const float* __restrict__ x,
                  const float* __restrict__ W,
                  const float* __restrict__ bias,
                  float* __restrict__ out)
{
    __shared__ Smem sm;
    const int tid = threadIdx.x;
    const int bid = blockIdx.x;

    if (bid < GW) {
        // =================== PRODUCER: staged dual GEMM ===================
        const int  lm   = tid >> 3;       // 0..31 (only <16 used for x, tid<128)
        const int  lkv  = tid & 7;        // k-float4 within chunk
        const int  lf   = tid >> 3;       // 0..31 (W row base; +32 for r=1)
        const int  mloc = tid >> 4;       // 0..15 output m row
        const int  fx   = tid & 15;       // output f group (4 floats)
        const bool xload = (tid < 128);

        for (int s = 0; s < GSTG; ++s) {
            const int tile = s * GW + bid;
            const int mt   = tile >> 2;          // 0..63
            const int f0   = (tile & 3) * BN;
            const int m0   = mt * BM;
            const int bi_b = mt >> 4;            // which b this m-tile belongs to

            float acc1[4] = {0.f, 0.f, 0.f, 0.f};
            float acc2[4] = {0.f, 0.f, 0.f, 0.f};

            float4 rx = make_float4(0.f, 0.f, 0.f, 0.f);
            float4 rw1[2], rw2[2];

            // prologue: chunk 0 -> regs
            if (xload)
                rx = *(const float4*)&x[(size_t)(m0 + lm) * EE + lkv * 4];
            #pragma unroll
            for (int r = 0; r < 2; ++r) {
                const float* wrow = W + (size_t)(f0 + lf + r * 32) * (2 * EE) + lkv * 4;
                rw1[r] = *(const float4*)(wrow);
                rw2[r] = *(const float4*)(wrow + EE);
            }

            for (int t = 0; t < NT; ++t) {
                __syncthreads();   // previous consumers of smem done
                if (xload) {
                    sm.g.x[lkv * 4 + 0][lm] = rx.x;
                    sm.g.x[lkv * 4 + 1][lm] = rx.y;
                    sm.g.x[lkv * 4 + 2][lm] = rx.z;
                    sm.g.x[lkv * 4 + 3][lm] = rx.w;
                }
                #pragma unroll
                for (int r = 0; r < 2; ++r) {
                    int f = lf + r * 32;
                    sm.g.w1[lkv * 4 + 0][f] = rw1[r].x;
                    sm.g.w1[lkv * 4 + 1][f] = rw1[r].y;
                    sm.g.w1[lkv * 4 + 2][f] = rw1[r].z;
                    sm.g.w1[lkv * 4 + 3][f] = rw1[r].w;
                    sm.g.w2[lkv * 4 + 0][f] = rw2[r].x;
                    sm.g.w2[lkv * 4 + 1][f] = rw2[r].y;
                    sm.g.w2[lkv * 4 + 2][f] = rw2[r].z;
                    sm.g.w2[lkv * 4 + 3][f] = rw2[r].w;
                }
                __syncthreads();

                if (t + 1 < NT) {   // prefetch next chunk
                    const int k0 = (t + 1) * BK;
                    if (xload)
                        rx = *(const float4*)&x[(size_t)(m0 + lm) * EE + k0 + lkv * 4];
                    #pragma unroll
                    for (int r = 0; r < 2; ++r) {
                        const float* wrow = W + (size_t)(f0 + lf + r * 32) * (2 * EE) + k0 + lkv * 4;
                        rw1[r] = *(const float4*)(wrow);
                        rw2[r] = *(const float4*)(wrow + EE);
                    }
                }

                #pragma unroll
                for (int k = 0; k < BK; ++k) {
                    float a  = sm.g.x[k][mloc];
                    float4 b1 = *(const float4*)&sm.g.w1[k][fx * 4];
                    float4 b2 = *(const float4*)&sm.g.w2[k][fx * 4];
                    acc1[0] += a * b1.x; acc1[1] += a * b1.y;
                    acc1[2] += a * b1.z; acc1[3] += a * b1.w;
                    acc2[0] += a * b2.x; acc2[1] += a * b2.y;
                    acc2[2] += a * b2.z; acc2[3] += a * b2.w;
                }
            }

            // epilogue: store pi / (pj + bias), then publish
            float4 bv = *(const float4*)&bias[f0 + fx * 4];
            const size_t o = (size_t)(m0 + mloc) * EE + f0 + fx * 4;
            *(float4*)&g_pi [o] = make_float4(acc1[0], acc1[1], acc1[2], acc1[3]);
            *(float4*)&g_pjb[o] = make_float4(acc2[0] + bv.x, acc2[1] + bv.y,
                                              acc2[2] + bv.z, acc2[3] + bv.w);
            __threadfence();
            __syncthreads();
            if (tid == 0)
                atomicAdd((int*)&g_b_done[bi_b], 1);
        }
    } else {
        // =================== CONSUMER: broadcast add ===================
        const int t   = bid - GW;
        const int b   = t >> 8;          // 256 tiles per b (in-order by b)
        const int rem = t & 255;
        const int i0  = (rem >> 3) * TI;
        const int j0  = (rem & 7) * TJ;
        const int e4  = tid & 63;
        const int jq  = tid >> 6;

        if (tid == 0) {
            int ns = 64;
            while (g_b_done[b] < BTGT) {
                __nanosleep(ns);
                if (ns < 2048) ns <<= 1;
            }
        }
        __syncthreads();
        __threadfence();   // acquire: order subsequent loads after flag observation

        const float4* pi4 = (const float4*)g_pi  + (size_t)(b * SS + i0) * E4;
        const float4* pj4 = (const float4*)g_pjb + (size_t)(b * SS + j0) * E4;

        // stage pjb tile in smem (2048 float4)
        #pragma unroll
        for (int r = 0; r < 8; ++r)
            sm.pj[tid + r * 256] = pj4[tid + r * 256];

        // pi tile -> registers
        float4 pi_r[TI];
        #pragma unroll
        for (int i = 0; i < TI; ++i)
            pi_r[i] = pi4[i * E4 + e4];

        __syncthreads();

        float4* out4 = (float4*)out + ((size_t)(b * SS + i0) * SS + j0) * E4;

        #pragma unroll
        for (int jj = 0; jj < TJ / 4; ++jj) {
            int j = jq + jj * 4;
            float4 c = sm.pj[j * E4 + e4];
            #pragma unroll
            for (int i = 0; i < TI; ++i) {
                float4 v = make_float4(pi_r[i].x + c.x, pi_r[i].y + c.y,
                                       pi_r[i].z + c.z, pi_r[i].w + c.w);
                __stcs(&out4[((size_t)i * SS + j) * E4 + e4], v);
            }
        }
    }

    // =================== exit: last block resets flags (graph-replay safe)
    __syncthreads();
    if (tid == 0) {
        __threadfence();
        unsigned r = atomicAdd(&g_exit_cnt, 1);
        if (r == GTOT - 1) {
            #pragma unroll
            for (int i = 0; i < BB; ++i) g_b_done[i] = 0;
            __threadfence();
            g_exit_cnt = 0;
        }
    }
}

// ---------------------------------------------------------------------------
extern "C" void kernel_launch(void* const* d_in, const int* in_sizes, int n_in,
                              void* d_out, int out_size)
{
    const float* x    = (const float*)d_in[0];   // component_repr [4,256,256]
    const float* W    = (const float*)d_in[1];   // W [256,512]
    const float* bias = (const float*)d_in[2];   // b [256]
    float* out = (float*)d_out;                  // [4,256,256,256]

    fused_kernel<<<GTOT, 256>>>(x, W, bias, out);
}

// round 4
// speedup vs baseline: 1.3089x; 1.3089x over previous
#include <cuda_runtime.h>

// Problem shape (fixed by the dataset)
#define BB 4
#define SS 256
#define EE 256
#define MM (BB * SS)        // 1024 "rows" of x

// Scratch: pi[m,f] and (pj[m,f] + b[f]) — 1 MB each
__device__ float g_pi [MM * EE];
__device__ float g_pjb[MM * EE];

// ---------------------------------------------------------------------------
// Kernel 1: dual GEMM, 256 small blocks (one tile each, single wave) so the
// kernel duration equals one tile's latency (~6-7us), not 16us.
//   pi[m,f]  = sum_e x[m,e] * W[f, e]
//   pjb[m,f] = sum_e x[m,e] * W[f, EE+e] + b[f]
// BM=16, BN=64, BK=32, 128 threads, thread tile 2(m) x 4(f) x 2 outputs.
// Double-buffered smem + register prefetch.
// ---------------------------------------------------------------------------
#define BM 16
#define BN 64
#define BK 32
#define NT (EE / BK)       // 8 K-chunks

#define XS 20              // s_x row stride (floats): [k][m], 16 used
#define WS 68              // s_w row stride (floats): [k][f], 64 used, 16B-aligned

__global__ __launch_bounds__(128)
void gemm_kernel(const float* __restrict__ x,
                 const float* __restrict__ W,
                 const float* __restrict__ bias)
{
    __shared__ float s_x [2][BK][XS];    // 5.1 KB
    __shared__ float s_w1[2][BK][WS];    // 17.4 KB
    __shared__ float s_w2[2][BK][WS];    // 17.4 KB

    const int bid = blockIdx.x;
    const int f0  = (bid & 3) * BN;
    const int m0  = (bid >> 2) * BM;
    const int tid = threadIdx.x;

    const int ty  = tid >> 4;    // 0..7  -> m (2 rows each)
    const int tx  = tid & 15;    // 0..15 -> f (4 cols each)

    // load indices
    const int lm  = tid >> 3;    // 0..15 (x tile row; only tid<128 all valid)
    const int lkv = tid & 7;     // k-float4 within row
    const int lf  = tid >> 3;    // 0..15 (W row base; +16*r)

    float4 rx, rw1[4], rw2[4];

    // ---- prologue: chunk 0 -> regs ----
    rx = *(const float4*)&x[(size_t)(m0 + lm) * EE + lkv * 4];
    #pragma unroll
    for (int r = 0; r < 4; ++r) {
        const float* wrow = W + (size_t)(f0 + lf + r * 16) * (2 * EE) + lkv * 4;
        rw1[r] = *(const float4*)(wrow);
        rw2[r] = *(const float4*)(wrow + EE);
    }
    // ---- store chunk 0 to buffer 0 ----
    {
        s_x[0][lkv * 4 + 0][lm] = rx.x;
        s_x[0][lkv * 4 + 1][lm] = rx.y;
        s_x[0][lkv * 4 + 2][lm] = rx.z;
        s_x[0][lkv * 4 + 3][lm] = rx.w;
        #pragma unroll
        for (int r = 0; r < 4; ++r) {
            int f = lf + r * 16;
            s_w1[0][lkv * 4 + 0][f] = rw1[r].x;
            s_w1[0][lkv * 4 + 1][f] = rw1[r].y;
            s_w1[0][lkv * 4 + 2][f] = rw1[r].z;
            s_w1[0][lkv * 4 + 3][f] = rw1[r].w;
            s_w2[0][lkv * 4 + 0][f] = rw2[r].x;
            s_w2[0][lkv * 4 + 1][f] = rw2[r].y;
            s_w2[0][lkv * 4 + 2][f] = rw2[r].z;
            s_w2[0][lkv * 4 + 3][f] = rw2[r].w;
        }
    }
    __syncthreads();

    float acc1[2][4] = {};
    float acc2[2][4] = {};

    for (int t = 0; t < NT; ++t) {
        const int buf = t & 1;

        // prefetch next chunk into registers
        if (t + 1 < NT) {
            const int k0 = (t + 1) * BK;
            rx = *(const float4*)&x[(size_t)(m0 + lm) * EE + k0 + lkv * 4];
            #pragma unroll
            for (int r = 0; r < 4; ++r) {
                const float* wrow = W + (size_t)(f0 + lf + r * 16) * (2 * EE) + k0 + lkv * 4;
                rw1[r] = *(const float4*)(wrow);
                rw2[r] = *(const float4*)(wrow + EE);
            }
        }

        // compute on current buffer
        #pragma unroll
        for (int k = 0; k < BK; ++k) {
            float a0 = s_x[buf][k][ty * 2 + 0];
            float a1 = s_x[buf][k][ty * 2 + 1];
            float4 b1 = *(const float4*)&s_w1[buf][k][tx * 4];
            float4 b2 = *(const float4*)&s_w2[buf][k][tx * 4];

            acc1[0][0] += a0 * b1.x; acc1[0][1] += a0 * b1.y;
            acc1[0][2] += a0 * b1.z; acc1[0][3] += a0 * b1.w;
            acc1[1][0] += a1 * b1.x; acc1[1][1] += a1 * b1.y;
            acc1[1][2] += a1 * b1.z; acc1[1][3] += a1 * b1.w;

            acc2[0][0] += a0 * b2.x; acc2[0][1] += a0 * b2.y;
            acc2[0][2] += a0 * b2.z; acc2[0][3] += a0 * b2.w;
            acc2[1][0] += a1 * b2.x; acc2[1][1] += a1 * b2.y;
            acc2[1][2] += a1 * b2.z; acc2[1][3] += a1 * b2.w;
        }

        // drain prefetch regs into the other buffer
        if (t + 1 < NT) {
            const int nbuf = (t + 1) & 1;
            __syncthreads();
            s_x[nbuf][lkv * 4 + 0][lm] = rx.x;
            s_x[nbuf][lkv * 4 + 1][lm] = rx.y;
            s_x[nbuf][lkv * 4 + 2][lm] = rx.z;
            s_x[nbuf][lkv * 4 + 3][lm] = rx.w;
            #pragma unroll
            for (int r = 0; r < 4; ++r) {
                int f = lf + r * 16;
                s_w1[nbuf][lkv * 4 + 0][f] = rw1[r].x;
                s_w1[nbuf][lkv * 4 + 1][f] = rw1[r].y;
                s_w1[nbuf][lkv * 4 + 2][f] = rw1[r].z;
                s_w1[nbuf][lkv * 4 + 3][f] = rw1[r].w;
                s_w2[nbuf][lkv * 4 + 0][f] = rw2[r].x;
                s_w2[nbuf][lkv * 4 + 1][f] = rw2[r].y;
                s_w2[nbuf][lkv * 4 + 2][f] = rw2[r].z;
                s_w2[nbuf][lkv * 4 + 3][f] = rw2[r].w;
            }
            __syncthreads();
        }
    }

    float4 bi = *(const float4*)&bias[f0 + tx * 4];

    #pragma unroll
    for (int i = 0; i < 2; ++i) {
        int m = m0 + ty * 2 + i;
        float4 v1 = make_float4(acc1[i][0], acc1[i][1], acc1[i][2], acc1[i][3]);
        float4 v2 = make_float4(acc2[i][0] + bi.x, acc2[i][1] + bi.y,
                                acc2[i][2] + bi.z, acc2[i][3] + bi.w);
        *(float4*)&g_pi [(size_t)m * EE + f0 + tx * 4] = v1;
        *(float4*)&g_pjb[(size_t)m * EE + f0 + tx * 4] = v2;
    }
}

// ---------------------------------------------------------------------------
// Kernel 2: broadcast add (identical to R2 best) — DRAM-write-bound.
// out[b,i,j,e] = pi[b,i,e] + pjb[b,j,e]
// ---------------------------------------------------------------------------
#define TI 8
#define TJ 32
#define E4 (EE / 4)   // 64 float4 per row

__global__ __launch_bounds__(256)
void add_kernel(float* __restrict__ out)
{
    __shared__ float4 s_pj[TJ * E4];   // 32 KB

    const int b   = blockIdx.z;
    const int i0  = blockIdx.y * TI;
    const int j0  = blockIdx.x * TJ;
    const int tid = threadIdx.x;
    const int e4  = tid & 63;
    const int jq  = tid >> 6;

    const float4* pi4 = (const float4*)g_pi  + (size_t)(b * SS + i0) * E4;
    const float4* pj4 = (const float4*)g_pjb + (size_t)(b * SS + j0) * E4;

    #pragma unroll
    for (int r = 0; r < 8; ++r)
        s_pj[tid + r * 256] = pj4[tid + r * 256];

    float4 pi_r[TI];
    #pragma unroll
    for (int i = 0; i < TI; ++i)
        pi_r[i] = pi4[i * E4 + e4];

    __syncthreads();

    float4* out4 = (float4*)out + ((size_t)(b * SS + i0) * SS + j0) * E4;

    #pragma unroll
    for (int jj = 0; jj < TJ / 4; ++jj) {
        int j = jq + jj * 4;
        float4 c = s_pj[j * E4 + e4];
        #pragma unroll
        for (int i = 0; i < TI; ++i) {
            float4 v = make_float4(pi_r[i].x + c.x, pi_r[i].y + c.y,
                                   pi_r[i].z + c.z, pi_r[i].w + c.w);
            __stcs(&out4[((size_t)i * SS + j) * E4 + e4], v);
        }
    }
}

// ---------------------------------------------------------------------------
extern "C" void kernel_launch(void* const* d_in, const int* in_sizes, int n_in,
                              void* d_out, int out_size)
{
    const float* x    = (const float*)d_in[0];   // component_repr [4,256,256]
    const float* W    = (const float*)d_in[1];   // W [256,512]
    const float* bias = (const float*)d_in[2];   // b [256]
    float* out = (float*)d_out;                  // [4,256,256,256]

    gemm_kernel<<<(MM / BM) * (EE / BN), 128>>>(x, W, bias);   // 256 blocks

    dim3 gAdd(SS / TJ, SS / TI, BB);             // 8 x 32 x 4
    add_kernel<<<gAdd, 256>>>(out);
}